// round 11
// baseline (speedup 1.0000x reference)
#include <cuda_runtime.h>
#include <math.h>

#define FULL 0xFFFFFFFFu
#define T_LEN 2048
#define CHUNKS 16          // 16 chunks x 128 elems per row
#define WPB 8              // warps per block; each warp owns 2 rows

// streaming sums for one chunk of one row
#define SUMS(e, m, i, sumt, sumidx)                                       \
    do {                                                                  \
        sumt = fmaf((m).x, (e).x, sumt); sumt = fmaf((m).y, (e).y, sumt); \
        sumt = fmaf((m).z, (e).z, sumt); sumt = fmaf((m).w, (e).w, sumt); \
        const float cnt_ = ((m).x + (m).y) + ((m).z + (m).w);             \
        const float base_ = (float)(128 * (i) + 4 * lane);                \
        sumidx = fmaf(cnt_, base_, sumidx);                               \
        sumidx += fmaf(3.f, (m).w, fmaf(2.f, (m).z, (m).y));              \
    } while (0)

// phase-1 body for one chunk: scan + gated exp; updates S and T
#define P1CHUNK(e, m, S, T)                                               \
    do {                                                                  \
        const float cnt = ((m).x + (m).y) + ((m).z + (m).w);              \
        float s = cnt;                                                    \
        _Pragma("unroll")                                                 \
        for (int off = 1; off < 32; off <<= 1) {                          \
            const float u = __shfl_up_sync(FULL, s, off);                 \
            if (lane >= off) s += u;                                      \
        }                                                                 \
        if (beta * (T) < 104.f) {                                         \
            float k = (T) + (s - cnt);                                    \
            if ((m).x > 0.5f) { S += expf(fmaf(mu, (e).x, -beta * k)); k += 1.f; } \
            if ((m).y > 0.5f) { S += expf(fmaf(mu, (e).y, -beta * k)); k += 1.f; } \
            if ((m).z > 0.5f) { S += expf(fmaf(mu, (e).z, -beta * k)); k += 1.f; } \
            if ((m).w > 0.5f) { S += expf(fmaf(mu, (e).w, -beta * k)); } \
        }                                                                 \
        T += __shfl_sync(FULL, s, 31);                                    \
    } while (0)

__global__ __launch_bounds__(256, 4)
void scpp_kernel(const float* __restrict__ event_times,
                 const float* __restrict__ input_mask,
                 const float* __restrict__ t0p,
                 const float* __restrict__ t1p,
                 const float* __restrict__ mup,
                 const float* __restrict__ betap,
                 float* __restrict__ out)
{
    const int lane = threadIdx.x & 31;
    const int w    = threadIdx.x >> 5;
    const int rowA = blockIdx.x * WPB + w;      // [0, 4096)
    const int rowB = rowA + 4096;               // [4096, 8192)

    const float mu   = log1pf(expf(__ldg(mup)));
    const float beta = log1pf(expf(__ldg(betap)));
    const float t0   = __ldg(t0p);
    const float t1   = __ldg(t1p);

    const float4* evA = reinterpret_cast<const float4*>(event_times + (size_t)rowA * T_LEN);
    const float4* mkA = reinterpret_cast<const float4*>(input_mask  + (size_t)rowA * T_LEN);
    const float4* evB = reinterpret_cast<const float4*>(event_times + (size_t)rowB * T_LEN);
    const float4* mkB = reinterpret_cast<const float4*>(input_mask  + (size_t)rowB * T_LEN);

    float sumtA = 0.f, sumidxA = 0.f, SA = 0.f, TA = 0.f;
    float sumtB = 0.f, sumidxB = 0.f, SB = 0.f, TB = 0.f;

    // ---- front-batch: phase-1 chunks of row A + first streaming slots ----
    const float4 a0e = evA[lane +  0], a1e = evA[lane + 32];
    const float4 a0m = mkA[lane +  0], a1m = mkA[lane + 32];

    // rolling 2-slot buffers for the streaming loop (chunk 2 and 3, both rows)
    float4 sEA[2], sMA[2], sEB[2], sMB[2];
    sEA[0] = evA[lane + 32*2]; sMA[0] = mkA[lane + 32*2];
    sEB[0] = evB[lane + 32*2]; sMB[0] = mkB[lane + 32*2];
    sEA[1] = evA[lane + 32*3]; sMA[1] = mkA[lane + 32*3];
    sEB[1] = evB[lane + 32*3]; sMB[1] = mkB[lane + 32*3];

    // ---- phase 1 row A (loads above in flight during the scan chains) ----
    SUMS(a0e, a0m, 0, sumtA, sumidxA);
    P1CHUNK(a0e, a0m, SA, TA);
    SUMS(a1e, a1m, 1, sumtA, sumidxA);
    P1CHUNK(a1e, a1m, SA, TA);

    // ---- phase 1 row B ----
    {
        const float4 b0e = evB[lane +  0], b1e = evB[lane + 32];
        const float4 b0m = mkB[lane +  0], b1m = mkB[lane + 32];
        SUMS(b0e, b0m, 0, sumtB, sumidxB);
        P1CHUNK(b0e, b0m, SB, TB);
        SUMS(b1e, b1m, 1, sumtB, sumidxB);
        P1CHUNK(b1e, b1m, SB, TB);
    }

    // ---- rare fallbacks (arbitrary masks): scan+exp only, reload-based ----
    if (beta * TA < 106.f) {
        for (int i = 2; i < CHUNKS && beta * TA < 106.f; i++) {
            const float4 e = evA[lane + 32 * i];
            const float4 m = mkA[lane + 32 * i];
            P1CHUNK(e, m, SA, TA);
        }
    }
    if (beta * TB < 106.f) {
        for (int i = 2; i < CHUNKS && beta * TB < 106.f; i++) {
            const float4 e = evB[lane + 32 * i];
            const float4 m = mkB[lane + 32 * i];
            P1CHUNK(e, m, SB, TB);
        }
    }

    // ---- streaming: chunks 2..15 of both rows, 2-slot rolling pipeline ----
    #pragma unroll
    for (int i = 2; i < CHUNKS; i++) {
        const int s = i & 1;
        const float4 eA = sEA[s], mA = sMA[s];
        const float4 eB = sEB[s], mB = sMB[s];
        // refill this slot with chunk i+2 (next+1 stays in flight)
        if (i + 2 < CHUNKS) {
            sEA[s] = evA[lane + 32*(i+2)]; sMA[s] = mkA[lane + 32*(i+2)];
            sEB[s] = evB[lane + 32*(i+2)]; sMB[s] = mkB[lane + 32*(i+2)];
        }
        SUMS(eA, mA, i, sumtA, sumidxA);
        SUMS(eB, mB, i, sumtB, sumidxB);
    }

    // ---- warp reductions (6 values) ----
    #pragma unroll
    for (int off = 16; off; off >>= 1) {
        sumtA   += __shfl_down_sync(FULL, sumtA,   off);
        sumidxA += __shfl_down_sync(FULL, sumidxA, off);
        SA      += __shfl_down_sync(FULL, SA,      off);
        sumtB   += __shfl_down_sync(FULL, sumtB,   off);
        sumidxB += __shfl_down_sync(FULL, sumidxB, off);
        SB      += __shfl_down_sync(FULL, SB,      off);
    }

    if (lane == 0) {
        const float emb = expf(-beta);
        const float eT0 = expf(mu * t0);

        const float llA = fmaf(mu, sumtA, -beta * sumidxA);
        float compA = fmaf(1.f - emb, SA, -eT0);
        compA += expf(fmaf(mu, t1, -beta * TA));   // exact 0 after underflow
        out[rowA] = llA - compA / mu;

        const float llB = fmaf(mu, sumtB, -beta * sumidxB);
        float compB = fmaf(1.f - emb, SB, -eT0);
        compB += expf(fmaf(mu, t1, -beta * TB));
        out[rowB] = llB - compB / mu;
    }
}

extern "C" void kernel_launch(void* const* d_in, const int* in_sizes, int n_in,
                              void* d_out, int out_size)
{
    const float* event_times = (const float*)d_in[0];
    // d_in[1] = spatial_locations : unused by the op
    const float* input_mask  = (const float*)d_in[2];
    const float* t0          = (const float*)d_in[3];
    const float* t1          = (const float*)d_in[4];
    const float* mu_param    = (const float*)d_in[5];
    const float* beta_param  = (const float*)d_in[6];
    float* out = (float*)d_out;

    const int n_rows = out_size;                 // 8192
    const int n_blocks = n_rows / (WPB * 2);     // 512
    scpp_kernel<<<n_blocks, 256>>>(event_times, input_mask,
                                   t0, t1, mu_param, beta_param, out);
}